// round 14
// baseline (speedup 1.0000x reference)
#include <cuda_runtime.h>
#include <cuda_fp16.h>
#include <cstdint>

#define N_NODES 100000
#define N_EDGES 1600000
#define D 128
#define CAP 64               // per-node edge bucket capacity (Poisson(16) tail-safe)

// Scratch (device globals: allocation-free per harness rules)
__device__ __half g_aggP[(size_t)N_NODES * D];   // agg, fp16
__device__ __half g_P0[(size_t)N_NODES * D];     // x / h1 plane
__device__ __half g_P1[(size_t)N_NODES * D];     // h0 plane
__device__ __half g_WH[3 * 128 * 256];           // [layer][n][k256] fp16
__device__ int    g_cnt[N_NODES];
__device__ int2   g_csr[(size_t)N_NODES * CAP];  // (src, weight-as-int), bucketed

// ===========================================================================
// small PTX helpers
// ===========================================================================
__device__ __forceinline__ uint32_t smem_u32(const void* p) {
    uint32_t a;
    asm("{ .reg .u64 t; cvta.to.shared.u64 t, %1; cvt.u32.u64 %0, t; }" : "=r"(a) : "l"(p));
    return a;
}
__device__ __forceinline__ void ldsm_x4(uint32_t* r, uint32_t addr) {
    asm volatile("ldmatrix.sync.aligned.m8n8.x4.shared.b16 {%0,%1,%2,%3}, [%4];"
                 : "=r"(r[0]), "=r"(r[1]), "=r"(r[2]), "=r"(r[3]) : "r"(addr));
}
__device__ __forceinline__ void ldsm_x2(uint32_t* r, uint32_t addr) {
    asm volatile("ldmatrix.sync.aligned.m8n8.x2.shared.b16 {%0,%1}, [%2];"
                 : "=r"(r[0]), "=r"(r[1]) : "r"(addr));
}
__device__ __forceinline__ void cp16(uint32_t dst, const void* src) {
    asm volatile("cp.async.cg.shared.global [%0], [%1], 16;" :: "r"(dst), "l"(src));
}
__device__ __forceinline__ void mma_f16(float* c, const uint32_t* a, const uint32_t* b) {
    asm volatile(
        "mma.sync.aligned.m16n8k16.row.col.f32.f16.f16.f32 "
        "{%0,%1,%2,%3}, {%4,%5,%6,%7}, {%8,%9}, {%0,%1,%2,%3};"
        : "+f"(c[0]), "+f"(c[1]), "+f"(c[2]), "+f"(c[3])
        : "r"(a[0]), "r"(a[1]), "r"(a[2]), "r"(a[3]), "r"(b[0]), "r"(b[1]));
}

// ===========================================================================
// Bucketed CSR build: single scatter pass (g_cnt pre-zeroed via memset)
// ===========================================================================
__global__ __launch_bounds__(256) void scatter_kernel(
    const int* __restrict__ src, const int* __restrict__ dst,
    const float* __restrict__ ew) {
    int e = blockIdx.x * blockDim.x + threadIdx.x;
    if (e >= N_EDGES) return;
    int d = dst[e];
    int p = atomicAdd(&g_cnt[d], 1);
    g_csr[(size_t)d * CAP + p] = make_int2(src[e], __float_as_int(ew[e]));
}

// ===========================================================================
// Pre-convert weights to fp16: g_WH[l][n][k256], k<128 Wrel, k>=128 Wroot
// ===========================================================================
__global__ __launch_bounds__(256) void presplit_w_kernel(
    const float* __restrict__ Wr0, const float* __restrict__ Wo0,
    const float* __restrict__ Wr1, const float* __restrict__ Wo1,
    const float* __restrict__ Wr2, const float* __restrict__ Wo2) {
    int idx = blockIdx.x * 256 + threadIdx.x;
    if (idx >= 3 * 128 * 256) return;
    int l = idx >> 15;
    int rem = idx & 32767;
    int n = rem >> 8;
    int k = rem & 255;
    const float* Wr = (l == 0) ? Wr0 : (l == 1) ? Wr1 : Wr2;
    const float* Wo = (l == 0) ? Wo0 : (l == 1) ? Wo1 : Wo2;
    float w = (k < 128) ? Wr[n * 128 + k] : Wo[n * 128 + (k - 128)];
    g_WH[idx] = __float2half_rn(w);
}

// x -> fp16 plane (P0)
__global__ __launch_bounds__(256) void split_x_kernel(const float* __restrict__ x) {
    int i = blockIdx.x * 256 + threadIdx.x;
    if (i >= N_NODES * D / 2) return;
    float2 v = reinterpret_cast<const float2*>(x)[i];
    __half2 h = __floats2half2_rn(v.x, v.y);
    reinterpret_cast<__half2*>(g_P0)[i] = h;
}

// ===========================================================================
// Bucketed aggregation: one warp/node, lane owns 4 channels.
// 8-edge unroll, dual accumulators (ILP 2), MLP 8, 32-bit offsets.
// fp32 accumulate, fp16 plane output.
// ===========================================================================
__device__ __forceinline__ void acc_edge(float4& acc, uint2 r, float w) {
    float2 a = __half22float2(*reinterpret_cast<const __half2*>(&r.x));
    float2 b = __half22float2(*reinterpret_cast<const __half2*>(&r.y));
    acc.x = fmaf(w, a.x, acc.x); acc.y = fmaf(w, a.y, acc.y);
    acc.z = fmaf(w, b.x, acc.z); acc.w = fmaf(w, b.y, acc.w);
}

__global__ __launch_bounds__(256) void agg_kernel(const __half* __restrict__ hP) {
    int node = (blockIdx.x * 256 + threadIdx.x) >> 5;
    if (node >= N_NODES) return;
    const int lane = threadIdx.x & 31;
    const int cnt = g_cnt[node];
    const int2* __restrict__ bucket = g_csr + (size_t)node * CAP;
    const char* base = reinterpret_cast<const char*>(hP) + lane * 8;

    float4 accA = make_float4(0.f, 0.f, 0.f, 0.f);
    float4 accB = make_float4(0.f, 0.f, 0.f, 0.f);
    int e = 0;
    for (; e + 8 <= cnt; e += 8) {
        int2 p[8];
#pragma unroll
        for (int q = 0; q < 8; ++q) p[q] = bucket[e + q];
        uint2 r[8];
#pragma unroll
        for (int q = 0; q < 8; ++q)
            r[q] = *reinterpret_cast<const uint2*>(base + ((uint32_t)p[q].x << 8));
#pragma unroll
        for (int q = 0; q < 8; q += 2) {
            acc_edge(accA, r[q],     __int_as_float(p[q].y));
            acc_edge(accB, r[q + 1], __int_as_float(p[q + 1].y));
        }
    }
    if (e + 4 <= cnt) {
        int2 p[4];
#pragma unroll
        for (int q = 0; q < 4; ++q) p[q] = bucket[e + q];
        uint2 r[4];
#pragma unroll
        for (int q = 0; q < 4; ++q)
            r[q] = *reinterpret_cast<const uint2*>(base + ((uint32_t)p[q].x << 8));
        acc_edge(accA, r[0], __int_as_float(p[0].y));
        acc_edge(accB, r[1], __int_as_float(p[1].y));
        acc_edge(accA, r[2], __int_as_float(p[2].y));
        acc_edge(accB, r[3], __int_as_float(p[3].y));
        e += 4;
    }
    for (; e < cnt; ++e) {
        int2 p = bucket[e];
        uint2 r = *reinterpret_cast<const uint2*>(base + ((uint32_t)p.x << 8));
        acc_edge(accA, r, __int_as_float(p.y));
    }

    accA.x += accB.x; accA.y += accB.y; accA.z += accB.z; accA.w += accB.w;
    __half2 a = __floats2half2_rn(accA.x, accA.y);
    __half2 b = __floats2half2_rn(accA.z, accA.w);
    uint2 st;
    st.x = *reinterpret_cast<uint32_t*>(&a);
    st.y = *reinterpret_cast<uint32_t*>(&b);
    *reinterpret_cast<uint2*>(reinterpret_cast<char*>(g_aggP) + (size_t)node * 256 + lane * 8) = st;
}

// ===========================================================================
// GEMM (round-10 config): out = maybe_relu( A @ W^T + b ), A = [aggP|hinP],
// K=256. CTA 128x128, 8 chunks of K=32, 3-stage cp.async pipeline.
// ===========================================================================
#define STAGE_BYTES 16384
#define PL_A 0
#define PL_WH 8192
#define OFF_STG 1024
#define GSMEM (OFF_STG + 3 * STAGE_BYTES)   // 50176

__device__ __forceinline__ uint32_t swz(int row, int grp) {
    return (uint32_t)row * 64 + (uint32_t)((grp ^ ((row >> 1) & 3)) << 4);
}

__device__ __forceinline__ void fill_stage(
    uint32_t stg, const __half* __restrict__ aP, int k0A,
    const __half* __restrict__ wh, int k0W,
    int row0, int tid) {
#pragma unroll
    for (int q = 0; q < 2; ++q) {
        const int i = tid * 2 + q;      // 0..511
        const int row = i >> 2;         // 0..127
        const int grp = i & 3;          // 16B group
        const uint32_t d = swz(row, grp);
        const int gr = row0 + row;
        if (gr < N_NODES) {
            cp16(stg + PL_A + d, aP + (size_t)gr * D + k0A + grp * 8);
        } else {
            asm volatile("st.shared.v4.b32 [%0], {%1,%1,%1,%1};"
                         :: "r"(stg + PL_A + d), "r"(0));
        }
        cp16(stg + PL_WH + d, wh + row * 256 + k0W + grp * 8);
    }
}

__global__ __launch_bounds__(256) void gemm_v3_kernel(
    const __half* __restrict__ hinP,
    const __half* __restrict__ WH,    // [128][256] this layer, fp16
    const float* __restrict__ bias,
    float* __restrict__ out,          // may be null
    __half* __restrict__ outP,        // may be null
    int do_relu) {
    extern __shared__ char smem[];
    const uint32_t sb = smem_u32(smem);
    const int tid = threadIdx.x;
    const int wid = tid >> 5;
    const int lane = tid & 31;
    const int row0 = blockIdx.x * 128;
    const int wm = wid >> 2;
    const int wn = wid & 3;

    if (tid < 128) ((float*)smem)[tid] = bias[tid];

    float acc[4][4][4];
#pragma unroll
    for (int i = 0; i < 4; ++i)
#pragma unroll
        for (int j = 0; j < 4; ++j)
#pragma unroll
            for (int r = 0; r < 4; ++r) acc[i][j][r] = 0.f;

#pragma unroll
    for (int t = 0; t < 3; ++t) {
        const __half* aP = (t < 4) ? g_aggP : hinP;
        fill_stage(sb + OFF_STG + t * STAGE_BYTES, aP, (t & 3) * 32,
                   WH, t * 32, row0, tid);
        asm volatile("cp.async.commit_group;" ::: "memory");
    }

    for (int t = 0; t < 8; ++t) {
        asm volatile("cp.async.wait_group 2;" ::: "memory");
        __syncthreads();

        const uint32_t stg = sb + OFF_STG + (t % 3) * STAGE_BYTES;
#pragma unroll
        for (int ks = 0; ks < 2; ++ks) {
            const int kb = ks * 16;
            uint32_t af[4][4];
#pragma unroll
            for (int i = 0; i < 4; ++i) {
                const int m0 = wm * 64 + i * 16;
                const int r = m0 + (lane & 7) + ((lane & 8) ? 8 : 0);
                const int g = (kb >> 3) + (lane >> 4);
                ldsm_x4(af[i], stg + PL_A + swz(r, g));
            }
            uint32_t bh[4][2];
#pragma unroll
            for (int j = 0; j < 4; ++j) {
                const int n0 = wn * 32 + j * 8;
                const int l15 = lane & 15;
                const int r = n0 + (l15 & 7);
                const int g = (kb >> 3) + (l15 >> 3);
                ldsm_x2(bh[j], stg + PL_WH + swz(r, g));
            }
#pragma unroll
            for (int i = 0; i < 4; ++i)
#pragma unroll
                for (int j = 0; j < 4; ++j)
                    mma_f16(acc[i][j], af[i], bh[j]);
        }
        __syncthreads();

        const int tn = t + 3;
        if (tn < 8) {
            const __half* aP = (tn < 4) ? g_aggP : hinP;
            fill_stage(sb + OFF_STG + (tn % 3) * STAGE_BYTES, aP, (tn & 3) * 32,
                       WH, tn * 32, row0, tid);
        }
        asm volatile("cp.async.commit_group;" ::: "memory");
    }

    // epilogue
    const float* sB = (const float*)smem;
    const int lr = lane >> 2;
    const int lc = (lane & 3) * 2;
#pragma unroll
    for (int i = 0; i < 4; ++i) {
        const int rows[2] = { row0 + wm * 64 + i * 16 + lr,
                              row0 + wm * 64 + i * 16 + lr + 8 };
#pragma unroll
        for (int j = 0; j < 4; ++j) {
            const int col = wn * 32 + j * 8 + lc;
            const float bx = sB[col], by = sB[col + 1];
#pragma unroll
            for (int hh = 0; hh < 2; ++hh) {
                const int r = rows[hh];
                if (r < N_NODES) {
                    float2 o;
                    o.x = acc[i][j][hh * 2 + 0] + bx;
                    o.y = acc[i][j][hh * 2 + 1] + by;
                    if (do_relu) { o.x = fmaxf(o.x, 0.f); o.y = fmaxf(o.y, 0.f); }
                    if (out)
                        *reinterpret_cast<float2*>(out + (size_t)r * D + col) = o;
                    if (outP) {
                        __half2 hp = __floats2half2_rn(o.x, o.y);
                        *reinterpret_cast<uint32_t*>(
                            reinterpret_cast<char*>(outP) + ((size_t)r * D + col) * 2) =
                            *reinterpret_cast<uint32_t*>(&hp);
                    }
                }
            }
        }
    }
}

// ===========================================================================
// Launch: memset+scatter on stream 0; plane/weight prep forked to stream 2.
// ===========================================================================
extern "C" void kernel_launch(void* const* d_in, const int* in_sizes, int n_in,
                              void* d_out, int out_size) {
    const float* x   = (const float*)d_in[0];
    const float* ew  = (const float*)d_in[1];
    const float* Wr0 = (const float*)d_in[2];
    const float* Wo0 = (const float*)d_in[3];
    const float* b0  = (const float*)d_in[4];
    const float* Wr1 = (const float*)d_in[5];
    const float* Wo1 = (const float*)d_in[6];
    const float* b1  = (const float*)d_in[7];
    const float* Wr2 = (const float*)d_in[8];
    const float* Wo2 = (const float*)d_in[9];
    const float* b2  = (const float*)d_in[10];
    const int* src   = (const int*)d_in[11];
    const int* dst   = (const int*)d_in[12];
    float* out = (float*)d_out;

    __half *p0 = nullptr, *p1 = nullptr, *whB = nullptr;
    int* cntp = nullptr;
    cudaGetSymbolAddress((void**)&p0, g_P0);
    cudaGetSymbolAddress((void**)&p1, g_P1);
    cudaGetSymbolAddress((void**)&whB, g_WH);
    cudaGetSymbolAddress((void**)&cntp, g_cnt);

    cudaFuncSetAttribute(gemm_v3_kernel, cudaFuncAttributeMaxDynamicSharedMemorySize, GSMEM);

    const int edge_blocks = (N_EDGES + 255) / 256;
    const int agg_blocks  = (N_NODES * 32 + 255) / 256;
    const int gemm_blocks = (N_NODES + 127) / 128;

    cudaStream_t s2;
    cudaStreamCreate(&s2);
    cudaEvent_t evFork, evJoin;
    cudaEventCreateWithFlags(&evFork, cudaEventDisableTiming);
    cudaEventCreateWithFlags(&evJoin, cudaEventDisableTiming);

    // Fork: plane/weight prep on s2 (independent of CSR build)
    cudaEventRecord(evFork, 0);
    cudaStreamWaitEvent(s2, evFork, 0);
    split_x_kernel<<<25000, 256, 0, s2>>>(x);
    presplit_w_kernel<<<384, 256, 0, s2>>>(Wr0, Wo0, Wr1, Wo1, Wr2, Wo2);
    cudaEventRecord(evJoin, s2);

    // Bucketed CSR build on default stream: memset + single scatter pass
    cudaMemsetAsync(cntp, 0, N_NODES * sizeof(int), 0);
    scatter_kernel<<<edge_blocks, 256>>>(src, dst, ew);

    // Join: agg needs P0 + buckets; GEMM needs WH
    cudaStreamWaitEvent(0, evJoin, 0);

    // Layer 0: A = [agg(P0) | P0] -> plane P1
    agg_kernel<<<agg_blocks, 256>>>(p0);
    gemm_v3_kernel<<<gemm_blocks, 256, GSMEM>>>(p0, whB, b0, nullptr, p1, 1);

    // Layer 1: A = [agg(P1) | P1] -> plane P0
    agg_kernel<<<agg_blocks, 256>>>(p1);
    gemm_v3_kernel<<<gemm_blocks, 256, GSMEM>>>(p1, whB + 32768, b1, nullptr, p0, 1);

    // Layer 2: A = [agg(P0) | P0] -> fp32 out
    agg_kernel<<<agg_blocks, 256>>>(p0);
    gemm_v3_kernel<<<gemm_blocks, 256, GSMEM>>>(p0, whB + 65536, b2, out, nullptr, 0);
}

// round 15
// speedup vs baseline: 1.1404x; 1.1404x over previous
#include <cuda_runtime.h>
#include <cuda_fp16.h>
#include <cstdint>

#define N_NODES 100000
#define N_EDGES 1600000
#define D 128
#define CAP 64               // per-node edge bucket capacity (Poisson(16) tail-safe)

// Scratch (device globals: allocation-free per harness rules)
__device__ __half g_aggP[(size_t)N_NODES * D];   // agg, fp16
__device__ __half g_P0[(size_t)N_NODES * D];     // x / h1 plane
__device__ __half g_P1[(size_t)N_NODES * D];     // h0 plane
__device__ __half g_WH[3 * 128 * 256];           // [layer][n][k256] fp16
__device__ int    g_cnt[N_NODES];
__device__ int2   g_csr[(size_t)N_NODES * CAP];  // (src, weight-as-int), bucketed

// ===========================================================================
// small PTX helpers
// ===========================================================================
__device__ __forceinline__ uint32_t smem_u32(const void* p) {
    uint32_t a;
    asm("{ .reg .u64 t; cvta.to.shared.u64 t, %1; cvt.u32.u64 %0, t; }" : "=r"(a) : "l"(p));
    return a;
}
__device__ __forceinline__ void ldsm_x4(uint32_t* r, uint32_t addr) {
    asm volatile("ldmatrix.sync.aligned.m8n8.x4.shared.b16 {%0,%1,%2,%3}, [%4];"
                 : "=r"(r[0]), "=r"(r[1]), "=r"(r[2]), "=r"(r[3]) : "r"(addr));
}
__device__ __forceinline__ void ldsm_x2(uint32_t* r, uint32_t addr) {
    asm volatile("ldmatrix.sync.aligned.m8n8.x2.shared.b16 {%0,%1}, [%2];"
                 : "=r"(r[0]), "=r"(r[1]) : "r"(addr));
}
__device__ __forceinline__ void cp16(uint32_t dst, const void* src) {
    asm volatile("cp.async.cg.shared.global [%0], [%1], 16;" :: "r"(dst), "l"(src));
}
__device__ __forceinline__ void mma_f16(float* c, const uint32_t* a, const uint32_t* b) {
    asm volatile(
        "mma.sync.aligned.m16n8k16.row.col.f32.f16.f16.f32 "
        "{%0,%1,%2,%3}, {%4,%5,%6,%7}, {%8,%9}, {%0,%1,%2,%3};"
        : "+f"(c[0]), "+f"(c[1]), "+f"(c[2]), "+f"(c[3])
        : "r"(a[0]), "r"(a[1]), "r"(a[2]), "r"(a[3]), "r"(b[0]), "r"(b[1]));
}

// ===========================================================================
// Bucketed CSR build: single scatter pass (g_cnt pre-zeroed via memset)
// ===========================================================================
__global__ __launch_bounds__(256) void scatter_kernel(
    const int* __restrict__ src, const int* __restrict__ dst,
    const float* __restrict__ ew) {
    int e = blockIdx.x * blockDim.x + threadIdx.x;
    if (e >= N_EDGES) return;
    int d = dst[e];
    int p = atomicAdd(&g_cnt[d], 1);
    g_csr[(size_t)d * CAP + p] = make_int2(src[e], __float_as_int(ew[e]));
}

// ===========================================================================
// Pre-convert weights to fp16: g_WH[l][n][k256], k<128 Wrel, k>=128 Wroot
// ===========================================================================
__global__ __launch_bounds__(256) void presplit_w_kernel(
    const float* __restrict__ Wr0, const float* __restrict__ Wo0,
    const float* __restrict__ Wr1, const float* __restrict__ Wo1,
    const float* __restrict__ Wr2, const float* __restrict__ Wo2) {
    int idx = blockIdx.x * 256 + threadIdx.x;
    if (idx >= 3 * 128 * 256) return;
    int l = idx >> 15;
    int rem = idx & 32767;
    int n = rem >> 8;
    int k = rem & 255;
    const float* Wr = (l == 0) ? Wr0 : (l == 1) ? Wr1 : Wr2;
    const float* Wo = (l == 0) ? Wo0 : (l == 1) ? Wo1 : Wo2;
    float w = (k < 128) ? Wr[n * 128 + k] : Wo[n * 128 + (k - 128)];
    g_WH[idx] = __float2half_rn(w);
}

// x -> fp16 plane (P0)
__global__ __launch_bounds__(256) void split_x_kernel(const float* __restrict__ x) {
    int i = blockIdx.x * 256 + threadIdx.x;
    if (i >= N_NODES * D / 2) return;
    float2 v = reinterpret_cast<const float2*>(x)[i];
    __half2 h = __floats2half2_rn(v.x, v.y);
    reinterpret_cast<__half2*>(g_P0)[i] = h;
}

// ===========================================================================
// Bucketed aggregation, half-warp per node: 16 lanes/node, uint4 (16B) lanes.
// One warp = 2 nodes; warp-instructions per edge halved vs warp-per-node.
// fp32 accumulate, fp16 plane output.
// ===========================================================================
__device__ __forceinline__ void accum8(float* acc, uint4 r, float w) {
    const __half2* h = reinterpret_cast<const __half2*>(&r);
#pragma unroll
    for (int q = 0; q < 4; ++q) {
        float2 f = __half22float2(h[q]);
        acc[2 * q]     = fmaf(w, f.x, acc[2 * q]);
        acc[2 * q + 1] = fmaf(w, f.y, acc[2 * q + 1]);
    }
}

__global__ __launch_bounds__(256) void agg_kernel(const __half* __restrict__ hP) {
    const int warp = (blockIdx.x * 256 + threadIdx.x) >> 5;
    const int lane = threadIdx.x & 31;
    const int half = lane >> 4;          // 0 or 1: which node this half-warp owns
    const int lane15 = lane & 15;        // channel group within node
    const int node = warp * 2 + half;    // grid sized so node < N_NODES always

    const int cnt = g_cnt[node];
    const int mx = max(cnt, __shfl_xor_sync(0xFFFFFFFFu, cnt, 16));
    const int2* __restrict__ bucket = g_csr + (size_t)node * CAP;
    const char* base = reinterpret_cast<const char*>(hP) + lane15 * 16;

    float acc[8] = {0.f, 0.f, 0.f, 0.f, 0.f, 0.f, 0.f, 0.f};
    int e = 0;
    for (; e + 2 <= mx; e += 2) {
        const int2 p0 = (e     < cnt) ? bucket[e]     : make_int2(0, 0);
        const int2 p1 = (e + 1 < cnt) ? bucket[e + 1] : make_int2(0, 0);
        const uint4 r0 = *reinterpret_cast<const uint4*>(base + ((uint32_t)p0.x << 8));
        const uint4 r1 = *reinterpret_cast<const uint4*>(base + ((uint32_t)p1.x << 8));
        accum8(acc, r0, __int_as_float(p0.y));   // p.y == 0 when inactive -> w = 0
        accum8(acc, r1, __int_as_float(p1.y));
    }
    if (e < mx) {
        const int2 p0 = (e < cnt) ? bucket[e] : make_int2(0, 0);
        const uint4 r0 = *reinterpret_cast<const uint4*>(base + ((uint32_t)p0.x << 8));
        accum8(acc, r0, __int_as_float(p0.y));
    }

    uint4 st;
    __half2 o0 = __floats2half2_rn(acc[0], acc[1]);
    __half2 o1 = __floats2half2_rn(acc[2], acc[3]);
    __half2 o2 = __floats2half2_rn(acc[4], acc[5]);
    __half2 o3 = __floats2half2_rn(acc[6], acc[7]);
    st.x = *reinterpret_cast<uint32_t*>(&o0);
    st.y = *reinterpret_cast<uint32_t*>(&o1);
    st.z = *reinterpret_cast<uint32_t*>(&o2);
    st.w = *reinterpret_cast<uint32_t*>(&o3);
    *reinterpret_cast<uint4*>(
        reinterpret_cast<char*>(g_aggP) + (size_t)node * 256 + lane15 * 16) = st;
}

// ===========================================================================
// GEMM (round-10 config): out = maybe_relu( A @ W^T + b ), A = [aggP|hinP],
// K=256. CTA 128x128, 8 chunks of K=32, 3-stage cp.async pipeline.
// ===========================================================================
#define STAGE_BYTES 16384
#define PL_A 0
#define PL_WH 8192
#define OFF_STG 1024
#define GSMEM (OFF_STG + 3 * STAGE_BYTES)   // 50176

__device__ __forceinline__ uint32_t swz(int row, int grp) {
    return (uint32_t)row * 64 + (uint32_t)((grp ^ ((row >> 1) & 3)) << 4);
}

__device__ __forceinline__ void fill_stage(
    uint32_t stg, const __half* __restrict__ aP, int k0A,
    const __half* __restrict__ wh, int k0W,
    int row0, int tid) {
#pragma unroll
    for (int q = 0; q < 2; ++q) {
        const int i = tid * 2 + q;      // 0..511
        const int row = i >> 2;         // 0..127
        const int grp = i & 3;          // 16B group
        const uint32_t d = swz(row, grp);
        const int gr = row0 + row;
        if (gr < N_NODES) {
            cp16(stg + PL_A + d, aP + (size_t)gr * D + k0A + grp * 8);
        } else {
            asm volatile("st.shared.v4.b32 [%0], {%1,%1,%1,%1};"
                         :: "r"(stg + PL_A + d), "r"(0));
        }
        cp16(stg + PL_WH + d, wh + row * 256 + k0W + grp * 8);
    }
}

__global__ __launch_bounds__(256) void gemm_v3_kernel(
    const __half* __restrict__ hinP,
    const __half* __restrict__ WH,    // [128][256] this layer, fp16
    const float* __restrict__ bias,
    float* __restrict__ out,          // may be null
    __half* __restrict__ outP,        // may be null
    int do_relu) {
    extern __shared__ char smem[];
    const uint32_t sb = smem_u32(smem);
    const int tid = threadIdx.x;
    const int wid = tid >> 5;
    const int lane = tid & 31;
    const int row0 = blockIdx.x * 128;
    const int wm = wid >> 2;
    const int wn = wid & 3;

    if (tid < 128) ((float*)smem)[tid] = bias[tid];

    float acc[4][4][4];
#pragma unroll
    for (int i = 0; i < 4; ++i)
#pragma unroll
        for (int j = 0; j < 4; ++j)
#pragma unroll
            for (int r = 0; r < 4; ++r) acc[i][j][r] = 0.f;

#pragma unroll
    for (int t = 0; t < 3; ++t) {
        const __half* aP = (t < 4) ? g_aggP : hinP;
        fill_stage(sb + OFF_STG + t * STAGE_BYTES, aP, (t & 3) * 32,
                   WH, t * 32, row0, tid);
        asm volatile("cp.async.commit_group;" ::: "memory");
    }

    for (int t = 0; t < 8; ++t) {
        asm volatile("cp.async.wait_group 2;" ::: "memory");
        __syncthreads();

        const uint32_t stg = sb + OFF_STG + (t % 3) * STAGE_BYTES;
#pragma unroll
        for (int ks = 0; ks < 2; ++ks) {
            const int kb = ks * 16;
            uint32_t af[4][4];
#pragma unroll
            for (int i = 0; i < 4; ++i) {
                const int m0 = wm * 64 + i * 16;
                const int r = m0 + (lane & 7) + ((lane & 8) ? 8 : 0);
                const int g = (kb >> 3) + (lane >> 4);
                ldsm_x4(af[i], stg + PL_A + swz(r, g));
            }
            uint32_t bh[4][2];
#pragma unroll
            for (int j = 0; j < 4; ++j) {
                const int n0 = wn * 32 + j * 8;
                const int l15 = lane & 15;
                const int r = n0 + (l15 & 7);
                const int g = (kb >> 3) + (l15 >> 3);
                ldsm_x2(bh[j], stg + PL_WH + swz(r, g));
            }
#pragma unroll
            for (int i = 0; i < 4; ++i)
#pragma unroll
                for (int j = 0; j < 4; ++j)
                    mma_f16(acc[i][j], af[i], bh[j]);
        }
        __syncthreads();

        const int tn = t + 3;
        if (tn < 8) {
            const __half* aP = (tn < 4) ? g_aggP : hinP;
            fill_stage(sb + OFF_STG + (tn % 3) * STAGE_BYTES, aP, (tn & 3) * 32,
                       WH, tn * 32, row0, tid);
        }
        asm volatile("cp.async.commit_group;" ::: "memory");
    }

    // epilogue
    const float* sB = (const float*)smem;
    const int lr = lane >> 2;
    const int lc = (lane & 3) * 2;
#pragma unroll
    for (int i = 0; i < 4; ++i) {
        const int rows[2] = { row0 + wm * 64 + i * 16 + lr,
                              row0 + wm * 64 + i * 16 + lr + 8 };
#pragma unroll
        for (int j = 0; j < 4; ++j) {
            const int col = wn * 32 + j * 8 + lc;
            const float bx = sB[col], by = sB[col + 1];
#pragma unroll
            for (int hh = 0; hh < 2; ++hh) {
                const int r = rows[hh];
                if (r < N_NODES) {
                    float2 o;
                    o.x = acc[i][j][hh * 2 + 0] + bx;
                    o.y = acc[i][j][hh * 2 + 1] + by;
                    if (do_relu) { o.x = fmaxf(o.x, 0.f); o.y = fmaxf(o.y, 0.f); }
                    if (out)
                        *reinterpret_cast<float2*>(out + (size_t)r * D + col) = o;
                    if (outP) {
                        __half2 hp = __floats2half2_rn(o.x, o.y);
                        *reinterpret_cast<uint32_t*>(
                            reinterpret_cast<char*>(outP) + ((size_t)r * D + col) * 2) =
                            *reinterpret_cast<uint32_t*>(&hp);
                    }
                }
            }
        }
    }
}

// ===========================================================================
// Launch: memset+scatter on stream 0; plane/weight prep forked to stream 2.
// ===========================================================================
extern "C" void kernel_launch(void* const* d_in, const int* in_sizes, int n_in,
                              void* d_out, int out_size) {
    const float* x   = (const float*)d_in[0];
    const float* ew  = (const float*)d_in[1];
    const float* Wr0 = (const float*)d_in[2];
    const float* Wo0 = (const float*)d_in[3];
    const float* b0  = (const float*)d_in[4];
    const float* Wr1 = (const float*)d_in[5];
    const float* Wo1 = (const float*)d_in[6];
    const float* b1  = (const float*)d_in[7];
    const float* Wr2 = (const float*)d_in[8];
    const float* Wo2 = (const float*)d_in[9];
    const float* b2  = (const float*)d_in[10];
    const int* src   = (const int*)d_in[11];
    const int* dst   = (const int*)d_in[12];
    float* out = (float*)d_out;

    __half *p0 = nullptr, *p1 = nullptr, *whB = nullptr;
    int* cntp = nullptr;
    cudaGetSymbolAddress((void**)&p0, g_P0);
    cudaGetSymbolAddress((void**)&p1, g_P1);
    cudaGetSymbolAddress((void**)&whB, g_WH);
    cudaGetSymbolAddress((void**)&cntp, g_cnt);

    cudaFuncSetAttribute(gemm_v3_kernel, cudaFuncAttributeMaxDynamicSharedMemorySize, GSMEM);

    const int edge_blocks = (N_EDGES + 255) / 256;
    const int agg_blocks  = (N_NODES / 2 * 32 + 255) / 256;  // 6250: 2 nodes/warp
    const int gemm_blocks = (N_NODES + 127) / 128;

    cudaStream_t s2;
    cudaStreamCreate(&s2);
    cudaEvent_t evFork, evJoin;
    cudaEventCreateWithFlags(&evFork, cudaEventDisableTiming);
    cudaEventCreateWithFlags(&evJoin, cudaEventDisableTiming);

    // Fork: plane/weight prep on s2 (independent of CSR build)
    cudaEventRecord(evFork, 0);
    cudaStreamWaitEvent(s2, evFork, 0);
    split_x_kernel<<<25000, 256, 0, s2>>>(x);
    presplit_w_kernel<<<384, 256, 0, s2>>>(Wr0, Wo0, Wr1, Wo1, Wr2, Wo2);
    cudaEventRecord(evJoin, s2);

    // Bucketed CSR build on default stream: memset + single scatter pass
    cudaMemsetAsync(cntp, 0, N_NODES * sizeof(int), 0);
    scatter_kernel<<<edge_blocks, 256>>>(src, dst, ew);

    // Join: agg needs P0 + buckets; GEMM needs WH
    cudaStreamWaitEvent(0, evJoin, 0);

    // Layer 0: A = [agg(P0) | P0] -> plane P1
    agg_kernel<<<agg_blocks, 256>>>(p0);
    gemm_v3_kernel<<<gemm_blocks, 256, GSMEM>>>(p0, whB, b0, nullptr, p1, 1);

    // Layer 1: A = [agg(P1) | P1] -> plane P0
    agg_kernel<<<agg_blocks, 256>>>(p1);
    gemm_v3_kernel<<<gemm_blocks, 256, GSMEM>>>(p1, whB + 32768, b1, nullptr, p0, 1);

    // Layer 2: A = [agg(P0) | P0] -> fp32 out
    agg_kernel<<<agg_blocks, 256>>>(p0);
    gemm_v3_kernel<<<gemm_blocks, 256, GSMEM>>>(p0, whB + 65536, b2, out, nullptr, 0);
}

// round 16
// speedup vs baseline: 1.1427x; 1.0019x over previous
#include <cuda_runtime.h>
#include <cuda_fp16.h>
#include <cstdint>

#define N_NODES 100000
#define N_EDGES 1600000
#define D 128
#define CAP 64               // per-node edge bucket capacity (Poisson(16) tail-safe)

// Scratch (device globals: allocation-free per harness rules)
__device__ __half g_aggP[(size_t)N_NODES * D];   // agg, fp16
__device__ __half g_P0[(size_t)N_NODES * D];     // x / h1 plane
__device__ __half g_P1[(size_t)N_NODES * D];     // h0 plane
__device__ __half g_WH[3 * 128 * 256];           // [layer][n][k256] fp16
__device__ int    g_cnt[N_NODES];
__device__ int2   g_csr[(size_t)N_NODES * CAP];  // (src, weight-as-int), bucketed

// ===========================================================================
// small PTX helpers
// ===========================================================================
__device__ __forceinline__ uint32_t smem_u32(const void* p) {
    uint32_t a;
    asm("{ .reg .u64 t; cvta.to.shared.u64 t, %1; cvt.u32.u64 %0, t; }" : "=r"(a) : "l"(p));
    return a;
}
__device__ __forceinline__ void ldsm_x4(uint32_t* r, uint32_t addr) {
    asm volatile("ldmatrix.sync.aligned.m8n8.x4.shared.b16 {%0,%1,%2,%3}, [%4];"
                 : "=r"(r[0]), "=r"(r[1]), "=r"(r[2]), "=r"(r[3]) : "r"(addr));
}
__device__ __forceinline__ void ldsm_x2(uint32_t* r, uint32_t addr) {
    asm volatile("ldmatrix.sync.aligned.m8n8.x2.shared.b16 {%0,%1}, [%2];"
                 : "=r"(r[0]), "=r"(r[1]) : "r"(addr));
}
__device__ __forceinline__ void cp16(uint32_t dst, const void* src) {
    asm volatile("cp.async.cg.shared.global [%0], [%1], 16;" :: "r"(dst), "l"(src));
}
__device__ __forceinline__ void mma_f16(float* c, const uint32_t* a, const uint32_t* b) {
    asm volatile(
        "mma.sync.aligned.m16n8k16.row.col.f32.f16.f16.f32 "
        "{%0,%1,%2,%3}, {%4,%5,%6,%7}, {%8,%9}, {%0,%1,%2,%3};"
        : "+f"(c[0]), "+f"(c[1]), "+f"(c[2]), "+f"(c[3])
        : "r"(a[0]), "r"(a[1]), "r"(a[2]), "r"(a[3]), "r"(b[0]), "r"(b[1]));
}

// ===========================================================================
// Bucketed CSR build: single scatter pass (g_cnt pre-zeroed via memset)
// ===========================================================================
__global__ __launch_bounds__(256) void scatter_kernel(
    const int* __restrict__ src, const int* __restrict__ dst,
    const float* __restrict__ ew) {
    int e = blockIdx.x * blockDim.x + threadIdx.x;
    if (e >= N_EDGES) return;
    int d = dst[e];
    int p = atomicAdd(&g_cnt[d], 1);
    g_csr[(size_t)d * CAP + p] = make_int2(src[e], __float_as_int(ew[e]));
}

// ===========================================================================
// Pre-convert weights to fp16: g_WH[l][n][k256], k<128 Wrel, k>=128 Wroot
// ===========================================================================
__global__ __launch_bounds__(256) void presplit_w_kernel(
    const float* __restrict__ Wr0, const float* __restrict__ Wo0,
    const float* __restrict__ Wr1, const float* __restrict__ Wo1,
    const float* __restrict__ Wr2, const float* __restrict__ Wo2) {
    int idx = blockIdx.x * 256 + threadIdx.x;
    if (idx >= 3 * 128 * 256) return;
    int l = idx >> 15;
    int rem = idx & 32767;
    int n = rem >> 8;
    int k = rem & 255;
    const float* Wr = (l == 0) ? Wr0 : (l == 1) ? Wr1 : Wr2;
    const float* Wo = (l == 0) ? Wo0 : (l == 1) ? Wo1 : Wo2;
    float w = (k < 128) ? Wr[n * 128 + k] : Wo[n * 128 + (k - 128)];
    g_WH[idx] = __float2half_rn(w);
}

// x -> fp16 plane (P0)
__global__ __launch_bounds__(256) void split_x_kernel(const float* __restrict__ x) {
    int i = blockIdx.x * 256 + threadIdx.x;
    if (i >= N_NODES * D / 2) return;
    float2 v = reinterpret_cast<const float2*>(x)[i];
    __half2 h = __floats2half2_rn(v.x, v.y);
    reinterpret_cast<__half2*>(g_P0)[i] = h;
}

// ===========================================================================
// Bucketed aggregation, half-warp per node: 16 lanes/node, uint4 (16B) lanes.
// One warp = 2 nodes. fp32 accumulate, fp16 plane output.
// ===========================================================================
__device__ __forceinline__ void accum8(float* acc, uint4 r, float w) {
    const __half2* h = reinterpret_cast<const __half2*>(&r);
#pragma unroll
    for (int q = 0; q < 4; ++q) {
        float2 f = __half22float2(h[q]);
        acc[2 * q]     = fmaf(w, f.x, acc[2 * q]);
        acc[2 * q + 1] = fmaf(w, f.y, acc[2 * q + 1]);
    }
}

__global__ __launch_bounds__(256) void agg_kernel(const __half* __restrict__ hP) {
    const int warp = (blockIdx.x * 256 + threadIdx.x) >> 5;
    const int lane = threadIdx.x & 31;
    const int half = lane >> 4;          // 0 or 1: which node this half-warp owns
    const int lane15 = lane & 15;        // channel group within node
    const int node = warp * 2 + half;    // grid sized so node < N_NODES always

    const int cnt = g_cnt[node];
    const int mx = max(cnt, __shfl_xor_sync(0xFFFFFFFFu, cnt, 16));
    const int2* __restrict__ bucket = g_csr + (size_t)node * CAP;
    const char* base = reinterpret_cast<const char*>(hP) + lane15 * 16;

    float acc[8] = {0.f, 0.f, 0.f, 0.f, 0.f, 0.f, 0.f, 0.f};
    int e = 0;
    for (; e + 2 <= mx; e += 2) {
        const int2 p0 = (e     < cnt) ? bucket[e]     : make_int2(0, 0);
        const int2 p1 = (e + 1 < cnt) ? bucket[e + 1] : make_int2(0, 0);
        const uint4 r0 = *reinterpret_cast<const uint4*>(base + ((uint32_t)p0.x << 8));
        const uint4 r1 = *reinterpret_cast<const uint4*>(base + ((uint32_t)p1.x << 8));
        accum8(acc, r0, __int_as_float(p0.y));   // p.y == 0 when inactive -> w = 0
        accum8(acc, r1, __int_as_float(p1.y));
    }
    if (e < mx) {
        const int2 p0 = (e < cnt) ? bucket[e] : make_int2(0, 0);
        const uint4 r0 = *reinterpret_cast<const uint4*>(base + ((uint32_t)p0.x << 8));
        accum8(acc, r0, __int_as_float(p0.y));
    }

    uint4 st;
    __half2 o0 = __floats2half2_rn(acc[0], acc[1]);
    __half2 o1 = __floats2half2_rn(acc[2], acc[3]);
    __half2 o2 = __floats2half2_rn(acc[4], acc[5]);
    __half2 o3 = __floats2half2_rn(acc[6], acc[7]);
    st.x = *reinterpret_cast<uint32_t*>(&o0);
    st.y = *reinterpret_cast<uint32_t*>(&o1);
    st.z = *reinterpret_cast<uint32_t*>(&o2);
    st.w = *reinterpret_cast<uint32_t*>(&o3);
    *reinterpret_cast<uint4*>(
        reinterpret_cast<char*>(g_aggP) + (size_t)node * 256 + lane15 * 16) = st;
}

// ===========================================================================
// GEMM: out = maybe_relu( A @ W^T + b ), A = [aggP|hinP], K=256.
// CTA 128x128, 8 chunks of K=32, 3-stage cp.async pipeline, 2 CTAs/SM.
// ===========================================================================
#define STAGE_BYTES 16384
#define PL_A 0
#define PL_WH 8192
#define OFF_STG 1024
#define GSMEM (OFF_STG + 3 * STAGE_BYTES)   // 50176

__device__ __forceinline__ uint32_t swz(int row, int grp) {
    return (uint32_t)row * 64 + (uint32_t)((grp ^ ((row >> 1) & 3)) << 4);
}

__device__ __forceinline__ void fill_stage(
    uint32_t stg, const __half* __restrict__ aP, int k0A,
    const __half* __restrict__ wh, int k0W,
    int row0, int tid) {
#pragma unroll
    for (int q = 0; q < 2; ++q) {
        const int i = tid * 2 + q;      // 0..511
        const int row = i >> 2;         // 0..127
        const int grp = i & 3;          // 16B group
        const uint32_t d = swz(row, grp);
        const int gr = row0 + row;
        if (gr < N_NODES) {
            cp16(stg + PL_A + d, aP + (size_t)gr * D + k0A + grp * 8);
        } else {
            asm volatile("st.shared.v4.b32 [%0], {%1,%1,%1,%1};"
                         :: "r"(stg + PL_A + d), "r"(0));
        }
        cp16(stg + PL_WH + d, wh + row * 256 + k0W + grp * 8);
    }
}

__global__ __launch_bounds__(256, 2) void gemm_v3_kernel(
    const __half* __restrict__ hinP,
    const __half* __restrict__ WH,    // [128][256] this layer, fp16
    const float* __restrict__ bias,
    float* __restrict__ out,          // may be null
    __half* __restrict__ outP,        // may be null
    int do_relu) {
    extern __shared__ char smem[];
    const uint32_t sb = smem_u32(smem);
    const int tid = threadIdx.x;
    const int wid = tid >> 5;
    const int lane = tid & 31;
    const int row0 = blockIdx.x * 128;
    const int wm = wid >> 2;
    const int wn = wid & 3;

    if (tid < 128) ((float*)smem)[tid] = bias[tid];

    float acc[4][4][4];
#pragma unroll
    for (int i = 0; i < 4; ++i)
#pragma unroll
        for (int j = 0; j < 4; ++j)
#pragma unroll
            for (int r = 0; r < 4; ++r) acc[i][j][r] = 0.f;

#pragma unroll
    for (int t = 0; t < 3; ++t) {
        const __half* aP = (t < 4) ? g_aggP : hinP;
        fill_stage(sb + OFF_STG + t * STAGE_BYTES, aP, (t & 3) * 32,
                   WH, t * 32, row0, tid);
        asm volatile("cp.async.commit_group;" ::: "memory");
    }

    for (int t = 0; t < 8; ++t) {
        asm volatile("cp.async.wait_group 2;" ::: "memory");
        __syncthreads();

        const uint32_t stg = sb + OFF_STG + (t % 3) * STAGE_BYTES;
#pragma unroll
        for (int ks = 0; ks < 2; ++ks) {
            const int kb = ks * 16;
            uint32_t af[4][4];
#pragma unroll
            for (int i = 0; i < 4; ++i) {
                const int m0 = wm * 64 + i * 16;
                const int r = m0 + (lane & 7) + ((lane & 8) ? 8 : 0);
                const int g = (kb >> 3) + (lane >> 4);
                ldsm_x4(af[i], stg + PL_A + swz(r, g));
            }
            uint32_t bh[4][2];
#pragma unroll
            for (int j = 0; j < 4; ++j) {
                const int n0 = wn * 32 + j * 8;
                const int l15 = lane & 15;
                const int r = n0 + (l15 & 7);
                const int g = (kb >> 3) + (l15 >> 3);
                ldsm_x2(bh[j], stg + PL_WH + swz(r, g));
            }
#pragma unroll
            for (int i = 0; i < 4; ++i)
#pragma unroll
                for (int j = 0; j < 4; ++j)
                    mma_f16(acc[i][j], af[i], bh[j]);
        }
        __syncthreads();

        const int tn = t + 3;
        if (tn < 8) {
            const __half* aP = (tn < 4) ? g_aggP : hinP;
            fill_stage(sb + OFF_STG + (tn % 3) * STAGE_BYTES, aP, (tn & 3) * 32,
                       WH, tn * 32, row0, tid);
        }
        asm volatile("cp.async.commit_group;" ::: "memory");
    }

    // epilogue
    const float* sB = (const float*)smem;
    const int lr = lane >> 2;
    const int lc = (lane & 3) * 2;
#pragma unroll
    for (int i = 0; i < 4; ++i) {
        const int rows[2] = { row0 + wm * 64 + i * 16 + lr,
                              row0 + wm * 64 + i * 16 + lr + 8 };
#pragma unroll
        for (int j = 0; j < 4; ++j) {
            const int col = wn * 32 + j * 8 + lc;
            const float bx = sB[col], by = sB[col + 1];
#pragma unroll
            for (int hh = 0; hh < 2; ++hh) {
                const int r = rows[hh];
                if (r < N_NODES) {
                    float2 o;
                    o.x = acc[i][j][hh * 2 + 0] + bx;
                    o.y = acc[i][j][hh * 2 + 1] + by;
                    if (do_relu) { o.x = fmaxf(o.x, 0.f); o.y = fmaxf(o.y, 0.f); }
                    if (out)
                        *reinterpret_cast<float2*>(out + (size_t)r * D + col) = o;
                    if (outP) {
                        __half2 hp = __floats2half2_rn(o.x, o.y);
                        *reinterpret_cast<uint32_t*>(
                            reinterpret_cast<char*>(outP) + ((size_t)r * D + col) * 2) =
                            *reinterpret_cast<uint32_t*>(&hp);
                    }
                }
            }
        }
    }
}

// ===========================================================================
// Launch: memset+scatter on stream 0; plane/weight prep forked to stream 2.
// ===========================================================================
extern "C" void kernel_launch(void* const* d_in, const int* in_sizes, int n_in,
                              void* d_out, int out_size) {
    const float* x   = (const float*)d_in[0];
    const float* ew  = (const float*)d_in[1];
    const float* Wr0 = (const float*)d_in[2];
    const float* Wo0 = (const float*)d_in[3];
    const float* b0  = (const float*)d_in[4];
    const float* Wr1 = (const float*)d_in[5];
    const float* Wo1 = (const float*)d_in[6];
    const float* b1  = (const float*)d_in[7];
    const float* Wr2 = (const float*)d_in[8];
    const float* Wo2 = (const float*)d_in[9];
    const float* b2  = (const float*)d_in[10];
    const int* src   = (const int*)d_in[11];
    const int* dst   = (const int*)d_in[12];
    float* out = (float*)d_out;

    __half *p0 = nullptr, *p1 = nullptr, *whB = nullptr;
    int* cntp = nullptr;
    cudaGetSymbolAddress((void**)&p0, g_P0);
    cudaGetSymbolAddress((void**)&p1, g_P1);
    cudaGetSymbolAddress((void**)&whB, g_WH);
    cudaGetSymbolAddress((void**)&cntp, g_cnt);

    cudaFuncSetAttribute(gemm_v3_kernel, cudaFuncAttributeMaxDynamicSharedMemorySize, GSMEM);

    const int edge_blocks = (N_EDGES + 255) / 256;
    const int agg_blocks  = (N_NODES / 2 * 32 + 255) / 256;  // 6250: 2 nodes/warp
    const int gemm_blocks = (N_NODES + 127) / 128;

    cudaStream_t s2;
    cudaStreamCreate(&s2);
    cudaEvent_t evFork, evJoin;
    cudaEventCreateWithFlags(&evFork, cudaEventDisableTiming);
    cudaEventCreateWithFlags(&evJoin, cudaEventDisableTiming);

    // Fork: plane/weight prep on s2 (independent of CSR build)
    cudaEventRecord(evFork, 0);
    cudaStreamWaitEvent(s2, evFork, 0);
    split_x_kernel<<<25000, 256, 0, s2>>>(x);
    presplit_w_kernel<<<384, 256, 0, s2>>>(Wr0, Wo0, Wr1, Wo1, Wr2, Wo2);
    cudaEventRecord(evJoin, s2);

    // Bucketed CSR build on default stream: memset + single scatter pass
    cudaMemsetAsync(cntp, 0, N_NODES * sizeof(int), 0);
    scatter_kernel<<<edge_blocks, 256>>>(src, dst, ew);

    // Join: agg needs P0 + buckets; GEMM needs WH
    cudaStreamWaitEvent(0, evJoin, 0);

    // Layer 0: A = [agg(P0) | P0] -> plane P1
    agg_kernel<<<agg_blocks, 256>>>(p0);
    gemm_v3_kernel<<<gemm_blocks, 256, GSMEM>>>(p0, whB, b0, nullptr, p1, 1);

    // Layer 1: A = [agg(P1) | P1] -> plane P0
    agg_kernel<<<agg_blocks, 256>>>(p1);
    gemm_v3_kernel<<<gemm_blocks, 256, GSMEM>>>(p1, whB + 32768, b1, nullptr, p0, 1);

    // Layer 2: A = [agg(P0) | P0] -> fp32 out
    agg_kernel<<<agg_blocks, 256>>>(p0);
    gemm_v3_kernel<<<gemm_blocks, 256, GSMEM>>>(p0, whB + 65536, b2, out, nullptr, 0);
}

// round 17
// speedup vs baseline: 1.1429x; 1.0002x over previous
#include <cuda_runtime.h>
#include <cuda_fp16.h>
#include <cstdint>

#define N_NODES 100000
#define N_EDGES 1600000
#define D 128
#define CAP 64               // per-node edge bucket capacity (Poisson(16) tail-safe)

// Scratch (device globals: allocation-free per harness rules)
__device__ __half g_aggP[(size_t)N_NODES * D];   // agg, fp16
__device__ __half g_P0[(size_t)N_NODES * D];     // x / h1 plane
__device__ __half g_P1[(size_t)N_NODES * D];     // h0 plane
__device__ __half g_WH[3 * 128 * 256];           // [layer][n][k256] fp16
__device__ int    g_cnt[N_NODES];
__device__ int2   g_csr[(size_t)N_NODES * CAP];  // (src, weight-as-int), bucketed

// ===========================================================================
// small PTX helpers
// ===========================================================================
__device__ __forceinline__ uint32_t smem_u32(const void* p) {
    uint32_t a;
    asm("{ .reg .u64 t; cvta.to.shared.u64 t, %1; cvt.u32.u64 %0, t; }" : "=r"(a) : "l"(p));
    return a;
}
__device__ __forceinline__ void ldsm_x4(uint32_t* r, uint32_t addr) {
    asm volatile("ldmatrix.sync.aligned.m8n8.x4.shared.b16 {%0,%1,%2,%3}, [%4];"
                 : "=r"(r[0]), "=r"(r[1]), "=r"(r[2]), "=r"(r[3]) : "r"(addr));
}
__device__ __forceinline__ void ldsm_x2(uint32_t* r, uint32_t addr) {
    asm volatile("ldmatrix.sync.aligned.m8n8.x2.shared.b16 {%0,%1}, [%2];"
                 : "=r"(r[0]), "=r"(r[1]) : "r"(addr));
}
__device__ __forceinline__ void cp16(uint32_t dst, const void* src) {
    asm volatile("cp.async.cg.shared.global [%0], [%1], 16;" :: "r"(dst), "l"(src));
}
__device__ __forceinline__ void mma_f16(float* c, const uint32_t* a, const uint32_t* b) {
    asm volatile(
        "mma.sync.aligned.m16n8k16.row.col.f32.f16.f16.f32 "
        "{%0,%1,%2,%3}, {%4,%5,%6,%7}, {%8,%9}, {%0,%1,%2,%3};"
        : "+f"(c[0]), "+f"(c[1]), "+f"(c[2]), "+f"(c[3])
        : "r"(a[0]), "r"(a[1]), "r"(a[2]), "r"(a[3]), "r"(b[0]), "r"(b[1]));
}

// ===========================================================================
// Bucketed CSR build: single scatter pass (g_cnt pre-zeroed via memset)
// ===========================================================================
__global__ __launch_bounds__(256) void scatter_kernel(
    const int* __restrict__ src, const int* __restrict__ dst,
    const float* __restrict__ ew) {
    int e = blockIdx.x * blockDim.x + threadIdx.x;
    if (e >= N_EDGES) return;
    int d = dst[e];
    int p = atomicAdd(&g_cnt[d], 1);
    g_csr[(size_t)d * CAP + p] = make_int2(src[e], __float_as_int(ew[e]));
}

// ===========================================================================
// Pre-convert weights to fp16: g_WH[l][n][k256], k<128 Wrel, k>=128 Wroot
// ===========================================================================
__global__ __launch_bounds__(256) void presplit_w_kernel(
    const float* __restrict__ Wr0, const float* __restrict__ Wo0,
    const float* __restrict__ Wr1, const float* __restrict__ Wo1,
    const float* __restrict__ Wr2, const float* __restrict__ Wo2) {
    int idx = blockIdx.x * 256 + threadIdx.x;
    if (idx >= 3 * 128 * 256) return;
    int l = idx >> 15;
    int rem = idx & 32767;
    int n = rem >> 8;
    int k = rem & 255;
    const float* Wr = (l == 0) ? Wr0 : (l == 1) ? Wr1 : Wr2;
    const float* Wo = (l == 0) ? Wo0 : (l == 1) ? Wo1 : Wo2;
    float w = (k < 128) ? Wr[n * 128 + k] : Wo[n * 128 + (k - 128)];
    g_WH[idx] = __float2half_rn(w);
}

// x -> fp16 plane (P0)
__global__ __launch_bounds__(256) void split_x_kernel(const float* __restrict__ x) {
    int i = blockIdx.x * 256 + threadIdx.x;
    if (i >= N_NODES * D / 2) return;
    float2 v = reinterpret_cast<const float2*>(x)[i];
    __half2 h = __floats2half2_rn(v.x, v.y);
    reinterpret_cast<__half2*>(g_P0)[i] = h;
}

// ===========================================================================
// Bucketed aggregation, half-warp per node: 16 lanes/node, uint4 (16B) lanes.
// One warp = 2 nodes. fp32 accumulate, fp16 plane output.
// ===========================================================================
__device__ __forceinline__ void accum8(float* acc, uint4 r, float w) {
    const __half2* h = reinterpret_cast<const __half2*>(&r);
#pragma unroll
    for (int q = 0; q < 4; ++q) {
        float2 f = __half22float2(h[q]);
        acc[2 * q]     = fmaf(w, f.x, acc[2 * q]);
        acc[2 * q + 1] = fmaf(w, f.y, acc[2 * q + 1]);
    }
}

__global__ __launch_bounds__(256) void agg_kernel(const __half* __restrict__ hP) {
    const int warp = (blockIdx.x * 256 + threadIdx.x) >> 5;
    const int lane = threadIdx.x & 31;
    const int half = lane >> 4;          // 0 or 1: which node this half-warp owns
    const int lane15 = lane & 15;        // channel group within node
    const int node = warp * 2 + half;    // grid sized so node < N_NODES always

    const int cnt = g_cnt[node];
    const int mx = max(cnt, __shfl_xor_sync(0xFFFFFFFFu, cnt, 16));
    const int2* __restrict__ bucket = g_csr + (size_t)node * CAP;
    const char* base = reinterpret_cast<const char*>(hP) + lane15 * 16;

    float acc[8] = {0.f, 0.f, 0.f, 0.f, 0.f, 0.f, 0.f, 0.f};
    int e = 0;
    for (; e + 2 <= mx; e += 2) {
        const int2 p0 = (e     < cnt) ? bucket[e]     : make_int2(0, 0);
        const int2 p1 = (e + 1 < cnt) ? bucket[e + 1] : make_int2(0, 0);
        const uint4 r0 = *reinterpret_cast<const uint4*>(base + ((uint32_t)p0.x << 8));
        const uint4 r1 = *reinterpret_cast<const uint4*>(base + ((uint32_t)p1.x << 8));
        accum8(acc, r0, __int_as_float(p0.y));   // p.y == 0 when inactive -> w = 0
        accum8(acc, r1, __int_as_float(p1.y));
    }
    if (e < mx) {
        const int2 p0 = (e < cnt) ? bucket[e] : make_int2(0, 0);
        const uint4 r0 = *reinterpret_cast<const uint4*>(base + ((uint32_t)p0.x << 8));
        accum8(acc, r0, __int_as_float(p0.y));
    }

    uint4 st;
    __half2 o0 = __floats2half2_rn(acc[0], acc[1]);
    __half2 o1 = __floats2half2_rn(acc[2], acc[3]);
    __half2 o2 = __floats2half2_rn(acc[4], acc[5]);
    __half2 o3 = __floats2half2_rn(acc[6], acc[7]);
    st.x = *reinterpret_cast<uint32_t*>(&o0);
    st.y = *reinterpret_cast<uint32_t*>(&o1);
    st.z = *reinterpret_cast<uint32_t*>(&o2);
    st.w = *reinterpret_cast<uint32_t*>(&o3);
    *reinterpret_cast<uint4*>(
        reinterpret_cast<char*>(g_aggP) + (size_t)node * 256 + lane15 * 16) = st;
}

// ===========================================================================
// GEMM: out = maybe_relu( A @ W^T + b ), A = [aggP|hinP], K=256.
// CTA 128x128, 8 chunks of K=32, 3-stage cp.async pipeline, 2 CTAs/SM.
// ===========================================================================
#define STAGE_BYTES 16384
#define PL_A 0
#define PL_WH 8192
#define OFF_STG 1024
#define GSMEM (OFF_STG + 3 * STAGE_BYTES)   // 50176

__device__ __forceinline__ uint32_t swz(int row, int grp) {
    return (uint32_t)row * 64 + (uint32_t)((grp ^ ((row >> 1) & 3)) << 4);
}

__device__ __forceinline__ void fill_stage(
    uint32_t stg, const __half* __restrict__ aP, int k0A,
    const __half* __restrict__ wh, int k0W,
    int row0, int tid) {
#pragma unroll
    for (int q = 0; q < 2; ++q) {
        const int i = tid * 2 + q;      // 0..511
        const int row = i >> 2;         // 0..127
        const int grp = i & 3;          // 16B group
        const uint32_t d = swz(row, grp);
        const int gr = row0 + row;
        if (gr < N_NODES) {
            cp16(stg + PL_A + d, aP + (size_t)gr * D + k0A + grp * 8);
        } else {
            asm volatile("st.shared.v4.b32 [%0], {%1,%1,%1,%1};"
                         :: "r"(stg + PL_A + d), "r"(0));
        }
        cp16(stg + PL_WH + d, wh + row * 256 + k0W + grp * 8);
    }
}

__global__ __launch_bounds__(256, 2) void gemm_v3_kernel(
    const __half* __restrict__ hinP,
    const __half* __restrict__ WH,    // [128][256] this layer, fp16
    const float* __restrict__ bias,
    float* __restrict__ out,          // may be null
    __half* __restrict__ outP,        // may be null
    int do_relu) {
    extern __shared__ char smem[];
    const uint32_t sb = smem_u32(smem);
    const int tid = threadIdx.x;
    const int wid = tid >> 5;
    const int lane = tid & 31;
    const int row0 = blockIdx.x * 128;
    const int wm = wid >> 2;
    const int wn = wid & 3;

    if (tid < 128) ((float*)smem)[tid] = bias[tid];

    float acc[4][4][4];
#pragma unroll
    for (int i = 0; i < 4; ++i)
#pragma unroll
        for (int j = 0; j < 4; ++j)
#pragma unroll
            for (int r = 0; r < 4; ++r) acc[i][j][r] = 0.f;

#pragma unroll
    for (int t = 0; t < 3; ++t) {
        const __half* aP = (t < 4) ? g_aggP : hinP;
        fill_stage(sb + OFF_STG + t * STAGE_BYTES, aP, (t & 3) * 32,
                   WH, t * 32, row0, tid);
        asm volatile("cp.async.commit_group;" ::: "memory");
    }

    for (int t = 0; t < 8; ++t) {
        asm volatile("cp.async.wait_group 2;" ::: "memory");
        __syncthreads();

        const uint32_t stg = sb + OFF_STG + (t % 3) * STAGE_BYTES;
#pragma unroll
        for (int ks = 0; ks < 2; ++ks) {
            const int kb = ks * 16;
            uint32_t af[4][4];
#pragma unroll
            for (int i = 0; i < 4; ++i) {
                const int m0 = wm * 64 + i * 16;
                const int r = m0 + (lane & 7) + ((lane & 8) ? 8 : 0);
                const int g = (kb >> 3) + (lane >> 4);
                ldsm_x4(af[i], stg + PL_A + swz(r, g));
            }
            uint32_t bh[4][2];
#pragma unroll
            for (int j = 0; j < 4; ++j) {
                const int n0 = wn * 32 + j * 8;
                const int l15 = lane & 15;
                const int r = n0 + (l15 & 7);
                const int g = (kb >> 3) + (l15 >> 3);
                ldsm_x2(bh[j], stg + PL_WH + swz(r, g));
            }
#pragma unroll
            for (int i = 0; i < 4; ++i)
#pragma unroll
                for (int j = 0; j < 4; ++j)
                    mma_f16(acc[i][j], af[i], bh[j]);
        }
        __syncthreads();

        const int tn = t + 3;
        if (tn < 8) {
            const __half* aP = (tn < 4) ? g_aggP : hinP;
            fill_stage(sb + OFF_STG + (tn % 3) * STAGE_BYTES, aP, (tn & 3) * 32,
                       WH, tn * 32, row0, tid);
        }
        asm volatile("cp.async.commit_group;" ::: "memory");
    }

    // epilogue
    const float* sB = (const float*)smem;
    const int lr = lane >> 2;
    const int lc = (lane & 3) * 2;
#pragma unroll
    for (int i = 0; i < 4; ++i) {
        const int rows[2] = { row0 + wm * 64 + i * 16 + lr,
                              row0 + wm * 64 + i * 16 + lr + 8 };
#pragma unroll
        for (int j = 0; j < 4; ++j) {
            const int col = wn * 32 + j * 8 + lc;
            const float bx = sB[col], by = sB[col + 1];
#pragma unroll
            for (int hh = 0; hh < 2; ++hh) {
                const int r = rows[hh];
                if (r < N_NODES) {
                    float2 o;
                    o.x = acc[i][j][hh * 2 + 0] + bx;
                    o.y = acc[i][j][hh * 2 + 1] + by;
                    if (do_relu) { o.x = fmaxf(o.x, 0.f); o.y = fmaxf(o.y, 0.f); }
                    if (out)
                        *reinterpret_cast<float2*>(out + (size_t)r * D + col) = o;
                    if (outP) {
                        __half2 hp = __floats2half2_rn(o.x, o.y);
                        *reinterpret_cast<uint32_t*>(
                            reinterpret_cast<char*>(outP) + ((size_t)r * D + col) * 2) =
                            *reinterpret_cast<uint32_t*>(&hp);
                    }
                }
            }
        }
    }
}

// ===========================================================================
// Launch: memset+scatter on stream 0; plane/weight prep forked to stream 2.
// ===========================================================================
extern "C" void kernel_launch(void* const* d_in, const int* in_sizes, int n_in,
                              void* d_out, int out_size) {
    const float* x   = (const float*)d_in[0];
    const float* ew  = (const float*)d_in[1];
    const float* Wr0 = (const float*)d_in[2];
    const float* Wo0 = (const float*)d_in[3];
    const float* b0  = (const float*)d_in[4];
    const float* Wr1 = (const float*)d_in[5];
    const float* Wo1 = (const float*)d_in[6];
    const float* b1  = (const float*)d_in[7];
    const float* Wr2 = (const float*)d_in[8];
    const float* Wo2 = (const float*)d_in[9];
    const float* b2  = (const float*)d_in[10];
    const int* src   = (const int*)d_in[11];
    const int* dst   = (const int*)d_in[12];
    float* out = (float*)d_out;

    __half *p0 = nullptr, *p1 = nullptr, *whB = nullptr;
    int* cntp = nullptr;
    cudaGetSymbolAddress((void**)&p0, g_P0);
    cudaGetSymbolAddress((void**)&p1, g_P1);
    cudaGetSymbolAddress((void**)&whB, g_WH);
    cudaGetSymbolAddress((void**)&cntp, g_cnt);

    cudaFuncSetAttribute(gemm_v3_kernel, cudaFuncAttributeMaxDynamicSharedMemorySize, GSMEM);

    const int edge_blocks = (N_EDGES + 255) / 256;
    const int agg_blocks  = (N_NODES / 2 * 32 + 255) / 256;  // 6250: 2 nodes/warp
    const int gemm_blocks = (N_NODES + 127) / 128;

    cudaStream_t s2;
    cudaStreamCreate(&s2);
    cudaEvent_t evFork, evJoin;
    cudaEventCreateWithFlags(&evFork, cudaEventDisableTiming);
    cudaEventCreateWithFlags(&evJoin, cudaEventDisableTiming);

    // Fork: plane/weight prep on s2 (independent of CSR build)
    cudaEventRecord(evFork, 0);
    cudaStreamWaitEvent(s2, evFork, 0);
    split_x_kernel<<<25000, 256, 0, s2>>>(x);
    presplit_w_kernel<<<384, 256, 0, s2>>>(Wr0, Wo0, Wr1, Wo1, Wr2, Wo2);
    cudaEventRecord(evJoin, s2);

    // Bucketed CSR build on default stream: memset + single scatter pass
    cudaMemsetAsync(cntp, 0, N_NODES * sizeof(int), 0);
    scatter_kernel<<<edge_blocks, 256>>>(src, dst, ew);

    // Join: agg needs P0 + buckets; GEMM needs WH
    cudaStreamWaitEvent(0, evJoin, 0);

    // Layer 0: A = [agg(P0) | P0] -> plane P1
    agg_kernel<<<agg_blocks, 256>>>(p0);
    gemm_v3_kernel<<<gemm_blocks, 256, GSMEM>>>(p0, whB, b0, nullptr, p1, 1);

    // Layer 1: A = [agg(P1) | P1] -> plane P0
    agg_kernel<<<agg_blocks, 256>>>(p1);
    gemm_v3_kernel<<<gemm_blocks, 256, GSMEM>>>(p1, whB + 32768, b1, nullptr, p0, 1);

    // Layer 2: A = [agg(P0) | P0] -> fp32 out
    agg_kernel<<<agg_blocks, 256>>>(p0);
    gemm_v3_kernel<<<gemm_blocks, 256, GSMEM>>>(p0, whB + 65536, b2, out, nullptr, 0);
}